// round 10
// baseline (speedup 1.0000x reference)
#include <cuda_runtime.h>
#include <cuda_bf16.h>

#define SEQL 601
#define BATCH 512
#define ZS 100
#define FLATD 5
#define HID 256
#define IN1 105  // ZS + FLATD
#define TPB 1024

// ---------------- scratch (__device__ globals; no allocation) ----------------
// LSTM weights repacked to bf16: [k][u][gate], each uint = (bf16 w_ih | bf16 w_hh << 16)
__device__ unsigned g_w1[HID * HID * 4];
__device__ unsigned g_w2[HID * HID * 4];
__device__ float g_b1[HID * 4];      // [u][gate] = b_ih + b_hh  (fp32)
__device__ float g_b2[HID * 4];
__device__ float g_fc1t[IN1 * HID];  // [k][n]  (transposed fc1_w, fp32)

// ---------------- weight repack kernel (cheap, runs every launch) ------------
__global__ void repack_kernel(const float* __restrict__ w_ih1,
                              const float* __restrict__ w_hh1,
                              const float* __restrict__ w_ih2,
                              const float* __restrict__ w_hh2,
                              const float* __restrict__ b_ih1,
                              const float* __restrict__ b_hh1,
                              const float* __restrict__ b_ih2,
                              const float* __restrict__ b_hh2,
                              const float* __restrict__ fc1_w) {
    int idx = blockIdx.x * blockDim.x + threadIdx.x;
    const int NP = HID * HID * 4;  // 262144 pairs per LSTM
    if (idx < 2 * NP) {
        int m = idx / NP;
        int e = idx % NP;
        int g = e & 3;
        int u = (e >> 2) & (HID - 1);
        int k = e >> 10;
        const float* wih = m ? w_ih2 : w_ih1;
        const float* whh = m ? w_hh2 : w_hh1;
        unsigned a = (unsigned)__bfloat16_as_ushort(__float2bfloat16(wih[(g * HID + u) * HID + k]));
        unsigned b = (unsigned)__bfloat16_as_ushort(__float2bfloat16(whh[(g * HID + u) * HID + k]));
        unsigned* dst = m ? g_w2 : g_w1;
        dst[e] = a | (b << 16);
    } else {
        int e = idx - 2 * NP;
        if (e < 2 * HID * 4) {
            int which = e / (HID * 4);
            int r = e % (HID * 4);
            int g = r & 3, u = r >> 2;
            if (which == 0)
                g_b1[r] = b_ih1[g * HID + u] + b_hh1[g * HID + u];
            else
                g_b2[r] = b_ih2[g * HID + u] + b_hh2[g * HID + u];
        } else {
            e -= 2 * HID * 4;
            if (e < IN1 * HID) {
                int n = e % HID, k = e / HID;
                g_fc1t[k * HID + n] = fc1_w[n * IN1 + k];
            }
        }
    }
}

// ---------------- activations -------------------------------------------------
__device__ __forceinline__ float sigm_f(float x) {
    return __fdividef(1.0f, 1.0f + __expf(-x));
}
__device__ __forceinline__ float tanh_f(float x) {
    float e = __expf(-2.0f * x);
    return __fdividef(2.0f, 1.0f + e) - 1.0f;
}

// ---------------- f32x2 helpers -----------------------------------------------
__device__ __forceinline__ unsigned long long cvtw(unsigned c) {
    unsigned lo = c << 16;
    unsigned hi = c & 0xffff0000u;
    unsigned long long p;
    asm("mov.b64 %0, {%1, %2};" : "=l"(p) : "r"(lo), "r"(hi));
    return p;
}
__device__ __forceinline__ void fma2(unsigned long long& acc, unsigned long long w,
                                     unsigned long long xh) {
    asm("fma.rn.f32x2 %0, %1, %2, %3;" : "=l"(acc) : "l"(w), "l"(xh), "l"(acc));
}
__device__ __forceinline__ float redu0(unsigned long long a) {
    unsigned lo, hi;
    asm("mov.b64 {%0, %1}, %2;" : "=r"(lo), "=r"(hi) : "l"(a));
    return __uint_as_float(lo) + __uint_as_float(hi);
}

// ---------------- LSTM accumulate over this quarter's 32 k2-iters -------------
// w: weight base offset to this quarter's first k ([k][u] uint4)
// x0..x3: per-row (x,h)-pair pointers, offset to this quarter's first k2
// acc[g*4+r]
__device__ __forceinline__ void lstm_accum_q(const uint4* __restrict__ w,
                                             const ulonglong2* __restrict__ x0,
                                             const ulonglong2* __restrict__ x1,
                                             const ulonglong2* __restrict__ x2,
                                             const ulonglong2* __restrict__ x3,
                                             int u, unsigned long long* acc) {
#pragma unroll 2
    for (int k2 = 0; k2 < 32; k2++) {
        uint4 wA = w[(2 * k2 + 0) * HID + u];
        uint4 wB = w[(2 * k2 + 1) * HID + u];
        unsigned long long wiA = cvtw(wA.x), wfA = cvtw(wA.y), wgA = cvtw(wA.z), woA = cvtw(wA.w);
        unsigned long long wiB = cvtw(wB.x), wfB = cvtw(wB.y), wgB = cvtw(wB.z), woB = cvtw(wB.w);
        {
            ulonglong2 xv = x0[k2];
            fma2(acc[0], wiA, xv.x); fma2(acc[4], wfA, xv.x); fma2(acc[8],  wgA, xv.x); fma2(acc[12], woA, xv.x);
            fma2(acc[0], wiB, xv.y); fma2(acc[4], wfB, xv.y); fma2(acc[8],  wgB, xv.y); fma2(acc[12], woB, xv.y);
        }
        {
            ulonglong2 xv = x1[k2];
            fma2(acc[1], wiA, xv.x); fma2(acc[5], wfA, xv.x); fma2(acc[9],  wgA, xv.x); fma2(acc[13], woA, xv.x);
            fma2(acc[1], wiB, xv.y); fma2(acc[5], wfB, xv.y); fma2(acc[9],  wgB, xv.y); fma2(acc[13], woB, xv.y);
        }
        {
            ulonglong2 xv = x2[k2];
            fma2(acc[2], wiA, xv.x); fma2(acc[6], wfA, xv.x); fma2(acc[10], wgA, xv.x); fma2(acc[14], woA, xv.x);
            fma2(acc[2], wiB, xv.y); fma2(acc[6], wfB, xv.y); fma2(acc[10], wgB, xv.y); fma2(acc[14], woB, xv.y);
        }
        {
            ulonglong2 xv = x3[k2];
            fma2(acc[3], wiA, xv.x); fma2(acc[7], wfA, xv.x); fma2(acc[11], wgA, xv.x); fma2(acc[15], woA, xv.x);
            fma2(acc[3], wiB, xv.y); fma2(acc[7], wfB, xv.y); fma2(acc[11], wgB, xv.y); fma2(acc[15], woB, xv.y);
        }
    }
}

// ---------------- main persistent kernel: CTA owns 4 batch rows ---------------
// 1024 threads: thread = (u, quarter q). quarter q: k in [64q, 64q+64).
// Activations distributed: thread (u,q) finalizes row q.
__global__ void __launch_bounds__(TPB, 1) gen_kernel(
    const float* __restrict__ z,         // [B][S][ZS]
    const float* __restrict__ prev_gen,  // [B][FLATD]
    const float* __restrict__ fc1_b,     // [HID]
    const float* __restrict__ fc2_w,     // [FLATD][HID]
    const float* __restrict__ fc2_b,     // [FLATD]
    float* __restrict__ out)             // [B][S][FLATD]
{
    extern __shared__ __align__(16) float sm[];
    float2 (*A1)[HID] = (float2(*)[HID])(sm);              // 4*256 float2 = 2048 f
    float2 (*A2)[HID] = (float2(*)[HID])(sm + 4096);       // 2048 f
    float* red = sm + 8192;                                 // [j=16][q=4][u=256] = 16384 f
    float (*insm)[112] = (float(*)[112])(sm + 8192 + 16384);  // 448 f

    const int tid = threadIdx.x;
    const int u = tid & (HID - 1);
    const int q = tid >> 8;
    const int b0 = blockIdx.x * 4;

    // init state: quarter q owns row q
    A1[q][u].y = 0.0f;  // h1 prev
    A2[q][u].y = 0.0f;  // h2 prev
    if (tid < 20) {
        int r = tid / 5, j = tid % 5;
        insm[r][ZS + j] = prev_gen[(b0 + r) * FLATD + j];
    }
    float c1 = 0.f, c2 = 0.f;  // cell state for row q, unit u
    const float fb = fc1_b[u];
    const float4 b1v = ((const float4*)g_b1)[u];
    const float4 b2v = ((const float4*)g_b2)[u];
    const uint4* w1q = (const uint4*)g_w1 + (size_t)q * 64 * HID;
    const uint4* w2q = (const uint4*)g_w2 + (size_t)q * 64 * HID;
    const int xoff = q * 32;  // in ulonglong2 units (2 k per element)
    __syncthreads();

    for (int t = 0; t < SEQL; ++t) {
        // ---- stage 1: stage z rows into smem ----
        if (tid < 4 * ZS) {
            int r = tid / ZS, k = tid % ZS;
            insm[r][k] = z[(size_t)(b0 + r) * (SEQL * ZS) + (size_t)t * ZS + k];
        }
        __syncthreads();  // B1: insm (z + prev) ready

        // ---- stage 2: fc1 + relu for row q -> A1.x ----
        {
            float a = fb;
#pragma unroll 5
            for (int k = 0; k < IN1; k++) a += g_fc1t[k * HID + u] * insm[q][k];
            A1[q][u].x = fmaxf(a, 0.0f);
        }
        __syncthreads();  // B2: A1 = (x, h1prev) ready

        // ---- stage 3: LSTM1 ----
        {
            unsigned long long acc[16];
#pragma unroll
            for (int j = 0; j < 16; j++) acc[j] = 0ull;
            lstm_accum_q(w1q, (const ulonglong2*)A1[0] + xoff, (const ulonglong2*)A1[1] + xoff,
                         (const ulonglong2*)A1[2] + xoff, (const ulonglong2*)A1[3] + xoff, u, acc);
#pragma unroll
            for (int j = 0; j < 16; j++) red[(j * 4 + q) * HID + u] = redu0(acc[j]);
            __syncthreads();  // B3: partials ready; all A1 reads done
            float gt[4];
#pragma unroll
            for (int g = 0; g < 4; g++) {
                int j = g * 4 + q;  // gate g, row q
                gt[g] = (red[(j * 4 + 0) * HID + u] + red[(j * 4 + 1) * HID + u]) +
                        (red[(j * 4 + 2) * HID + u] + red[(j * 4 + 3) * HID + u]);
            }
            float iv = sigm_f(gt[0] + b1v.x);
            float fv = sigm_f(gt[1] + b1v.y);
            float gv = tanh_f(gt[2] + b1v.z);
            float ov = sigm_f(gt[3] + b1v.w);
            float cn = fv * c1 + iv * gv;
            c1 = cn;
            float hv = ov * tanh_f(cn);
            A1[q][u].y = hv;  // h1 for step t+1
            A2[q][u].x = hv;  // h1 input to LSTM2 now
        }
        __syncthreads();  // B4: A2 = (h1, h2prev) ready

        // ---- stage 4: LSTM2 ----
        {
            unsigned long long acc[16];
#pragma unroll
            for (int j = 0; j < 16; j++) acc[j] = 0ull;
            lstm_accum_q(w2q, (const ulonglong2*)A2[0] + xoff, (const ulonglong2*)A2[1] + xoff,
                         (const ulonglong2*)A2[2] + xoff, (const ulonglong2*)A2[3] + xoff, u, acc);
#pragma unroll
            for (int j = 0; j < 16; j++) red[(j * 4 + q) * HID + u] = redu0(acc[j]);
            __syncthreads();  // B5
            float gt[4];
#pragma unroll
            for (int g = 0; g < 4; g++) {
                int j = g * 4 + q;
                gt[g] = (red[(j * 4 + 0) * HID + u] + red[(j * 4 + 1) * HID + u]) +
                        (red[(j * 4 + 2) * HID + u] + red[(j * 4 + 3) * HID + u]);
            }
            float iv = sigm_f(gt[0] + b2v.x);
            float fv = sigm_f(gt[1] + b2v.y);
            float gv = tanh_f(gt[2] + b2v.z);
            float ov = sigm_f(gt[3] + b2v.w);
            float cn = fv * c2 + iv * gv;
            c2 = cn;
            A2[q][u].y = ov * tanh_f(cn);
        }
        __syncthreads();  // B6: h2 ready

        // ---- stage 5: fc2 + tanh -> prev + output (20 of 32 warps) ----
        {
            int wid = tid >> 5, lane = tid & 31;
            if (wid < 20) {
                int j = wid >> 2, r = wid & 3;
                float s = 0.0f;
#pragma unroll
                for (int i = 0; i < 8; i++) {
                    int uu = lane + 32 * i;
                    s += fc2_w[j * HID + uu] * A2[r][uu].y;
                }
#pragma unroll
                for (int o = 16; o; o >>= 1) s += __shfl_down_sync(0xffffffffu, s, o);
                if (lane == 0) {
                    float v = tanh_f(s + fc2_b[j]);
                    insm[r][ZS + j] = v;
                    out[(size_t)(b0 + r) * (SEQL * FLATD) + (size_t)t * FLATD + j] = v;
                }
            }
        }
        // no barrier: stage1(t+1) and stage5 write disjoint smem; B1 orders both
        // before the fc1 reads; A2.y next written only after B5(t+1).
    }
}

// ---------------- launch ------------------------------------------------------
extern "C" void kernel_launch(void* const* d_in, const int* in_sizes, int n_in,
                              void* d_out, int out_size) {
    (void)in_sizes; (void)n_in; (void)out_size;
    const float* z        = (const float*)d_in[0];
    const float* prev_gen = (const float*)d_in[1];
    const float* fc1_w    = (const float*)d_in[2];
    const float* fc1_b    = (const float*)d_in[3];
    const float* w_ih1    = (const float*)d_in[4];
    const float* w_hh1    = (const float*)d_in[5];
    const float* b_ih1    = (const float*)d_in[6];
    const float* b_hh1    = (const float*)d_in[7];
    const float* w_ih2    = (const float*)d_in[8];
    const float* w_hh2    = (const float*)d_in[9];
    const float* b_ih2    = (const float*)d_in[10];
    const float* b_hh2    = (const float*)d_in[11];
    const float* fc2_w    = (const float*)d_in[12];
    const float* fc2_b    = (const float*)d_in[13];
    float* out = (float*)d_out;

    const int total = 2 * HID * HID * 4 + 2 * HID * 4 + IN1 * HID;
    repack_kernel<<<(total + 255) / 256, 256>>>(w_ih1, w_hh1, w_ih2, w_hh2,
                                                b_ih1, b_hh1, b_ih2, b_hh2, fc1_w);

    const int smem_bytes = (8192 + 16384 + 448) * (int)sizeof(float);  // ~98KB? no: 25024 f = 100096 B
    static int attr_done = 0;
    // setting the attribute is idempotent and not a stream op; safe under capture
    cudaFuncSetAttribute(gen_kernel, cudaFuncAttributeMaxDynamicSharedMemorySize, smem_bytes);
    (void)attr_done;

    gen_kernel<<<BATCH / 4, TPB, smem_bytes>>>(z, prev_gen, fc1_b, fc2_w, fc2_b, out);
}

// round 11
// speedup vs baseline: 1.0803x; 1.0803x over previous
#include <cuda_runtime.h>
#include <cuda_bf16.h>

#define SEQL 601
#define BATCH 512
#define ZS 100
#define FLATD 5
#define HID 256
#define IN1 105  // ZS + FLATD
#define TPB 512

// ---------------- scratch (__device__ globals; no allocation) ----------------
// LSTM weights repacked to bf16: [k][u][gate], each uint = (bf16 w_ih | bf16 w_hh << 16)
__device__ unsigned g_w1[HID * HID * 4];
__device__ unsigned g_w2[HID * HID * 4];
__device__ float g_b1[HID * 4];      // [u][gate] = b_ih + b_hh  (fp32)
__device__ float g_b2[HID * 4];
__device__ float g_fc1t[IN1 * HID];  // [k][n]  (transposed fc1_w, fp32)

// ---------------- weight repack kernel (cheap, runs every launch) ------------
__global__ void repack_kernel(const float* __restrict__ w_ih1,
                              const float* __restrict__ w_hh1,
                              const float* __restrict__ w_ih2,
                              const float* __restrict__ w_hh2,
                              const float* __restrict__ b_ih1,
                              const float* __restrict__ b_hh1,
                              const float* __restrict__ b_ih2,
                              const float* __restrict__ b_hh2,
                              const float* __restrict__ fc1_w) {
    int idx = blockIdx.x * blockDim.x + threadIdx.x;
    const int NP = HID * HID * 4;  // 262144 pairs per LSTM
    if (idx < 2 * NP) {
        int m = idx / NP;
        int e = idx % NP;
        int g = e & 3;
        int u = (e >> 2) & (HID - 1);
        int k = e >> 10;
        const float* wih = m ? w_ih2 : w_ih1;
        const float* whh = m ? w_hh2 : w_hh1;
        unsigned a = (unsigned)__bfloat16_as_ushort(__float2bfloat16(wih[(g * HID + u) * HID + k]));
        unsigned b = (unsigned)__bfloat16_as_ushort(__float2bfloat16(whh[(g * HID + u) * HID + k]));
        unsigned* dst = m ? g_w2 : g_w1;
        dst[e] = a | (b << 16);
    } else {
        int e = idx - 2 * NP;
        if (e < 2 * HID * 4) {
            int which = e / (HID * 4);
            int r = e % (HID * 4);
            int g = r & 3, u = r >> 2;
            if (which == 0)
                g_b1[r] = b_ih1[g * HID + u] + b_hh1[g * HID + u];
            else
                g_b2[r] = b_ih2[g * HID + u] + b_hh2[g * HID + u];
        } else {
            e -= 2 * HID * 4;
            if (e < IN1 * HID) {
                int n = e % HID, k = e / HID;
                g_fc1t[k * HID + n] = fc1_w[n * IN1 + k];
            }
        }
    }
}

// ---------------- activations -------------------------------------------------
__device__ __forceinline__ float sigm_f(float x) {
    return __fdividef(1.0f, 1.0f + __expf(-x));
}
__device__ __forceinline__ float tanh_f(float x) {
    float e = __expf(-2.0f * x);
    return __fdividef(2.0f, 1.0f + e) - 1.0f;
}

// ---------------- f32x2 helpers -----------------------------------------------
__device__ __forceinline__ unsigned long long cvtw(unsigned c) {
    unsigned lo = c << 16;
    unsigned hi = c & 0xffff0000u;
    unsigned long long p;
    asm("mov.b64 %0, {%1, %2};" : "=l"(p) : "r"(lo), "r"(hi));
    return p;
}
__device__ __forceinline__ void fma2(unsigned long long& acc, unsigned long long w,
                                     unsigned long long xh) {
    asm("fma.rn.f32x2 %0, %1, %2, %3;" : "=l"(acc) : "l"(w), "l"(xh), "l"(acc));
}
__device__ __forceinline__ float redu0(unsigned long long a) {
    unsigned lo, hi;
    asm("mov.b64 {%0, %1}, %2;" : "=r"(lo), "=r"(hi) : "l"(a));
    return __uint_as_float(lo) + __uint_as_float(hi);
}

// ---------------- cp.async helpers ---------------------------------------------
__device__ __forceinline__ unsigned sm_u32(const void* p) {
    return (unsigned)__cvta_generic_to_shared(p);
}
// Stage 4 k's (4 x 16B) of one chunk into one ring slot; one commit group.
__device__ __forceinline__ void issue4(unsigned sm, const uint4* src) {
#pragma unroll
    for (int kk = 0; kk < 4; kk++)
        asm volatile("cp.async.cg.shared.global [%0], [%1], 16;"
                     :: "r"(sm + kk * 8192), "l"(src + kk * HID) : "memory");
    asm volatile("cp.async.commit_group;" ::: "memory");
}

// ---------------- one k2 (2 k's) of LSTM math ----------------------------------
__device__ __forceinline__ void k2_block(uint4 wA, uint4 wB,
                                         ulonglong2 xv0, ulonglong2 xv1,
                                         ulonglong2 xv2, ulonglong2 xv3,
                                         unsigned long long* acc) {
    unsigned long long wi = cvtw(wA.x), wf = cvtw(wA.y), wg = cvtw(wA.z), wo = cvtw(wA.w);
    fma2(acc[0], wi, xv0.x); fma2(acc[4], wf, xv0.x); fma2(acc[8],  wg, xv0.x); fma2(acc[12], wo, xv0.x);
    fma2(acc[1], wi, xv1.x); fma2(acc[5], wf, xv1.x); fma2(acc[9],  wg, xv1.x); fma2(acc[13], wo, xv1.x);
    fma2(acc[2], wi, xv2.x); fma2(acc[6], wf, xv2.x); fma2(acc[10], wg, xv2.x); fma2(acc[14], wo, xv2.x);
    fma2(acc[3], wi, xv3.x); fma2(acc[7], wf, xv3.x); fma2(acc[11], wg, xv3.x); fma2(acc[15], wo, xv3.x);
    wi = cvtw(wB.x); wf = cvtw(wB.y); wg = cvtw(wB.z); wo = cvtw(wB.w);
    fma2(acc[0], wi, xv0.y); fma2(acc[4], wf, xv0.y); fma2(acc[8],  wg, xv0.y); fma2(acc[12], wo, xv0.y);
    fma2(acc[1], wi, xv1.y); fma2(acc[5], wf, xv1.y); fma2(acc[9],  wg, xv1.y); fma2(acc[13], wo, xv1.y);
    fma2(acc[2], wi, xv2.y); fma2(acc[6], wf, xv2.y); fma2(acc[10], wg, xv2.y); fma2(acc[14], wo, xv2.y);
    fma2(acc[3], wi, xv3.y); fma2(acc[7], wf, xv3.y); fma2(acc[11], wg, xv3.y); fma2(acc[15], wo, xv3.y);
}

// ---------------- dynamic smem layout (bytes) ----------------------------------
// ring : [0, 98304)           3 slots x (4 kl x 512 tid x 16B) = 3 x 32KB
// A1   : [98304, 106496)      float2[4][256]
// A2   : [106496, 114688)     float2[4][256]
// red  : [114688, 131072)     float[16][256]
// insm : [131072, 132864)     float[4][112]
#define SMEM_TOTAL 132864

// ---------------- main persistent kernel: CTA owns 4 batch rows ----------------
// 512 threads: thread = (u, half). half h: k in [128h, 128h+128).
// Weight stream: per-thread cp.async ring (depth 2), no barriers needed for it.
__global__ void __launch_bounds__(TPB, 1) gen_kernel(
    const float* __restrict__ z,         // [B][S][ZS]
    const float* __restrict__ prev_gen,  // [B][FLATD]
    const float* __restrict__ fc1_b,     // [HID]
    const float* __restrict__ fc2_w,     // [FLATD][HID]
    const float* __restrict__ fc2_b,     // [FLATD]
    float* __restrict__ out)             // [B][S][FLATD]
{
    extern __shared__ __align__(16) char smraw[];
    uint4* ring = (uint4*)smraw;
    float2 (*A1)[HID] = (float2(*)[HID])(smraw + 98304);
    float2 (*A2)[HID] = (float2(*)[HID])(smraw + 106496);
    float* red = (float*)(smraw + 114688);
    float (*insm)[112] = (float(*)[112])(smraw + 131072);

    const int tid = threadIdx.x;
    const int u = tid & (HID - 1);
    const int half = tid >> 8;
    const int b0 = blockIdx.x * 4;

    if (!half) {
#pragma unroll
        for (int r = 0; r < 4; r++) {
            A1[r][u].y = 0.0f;
            A2[r][u].y = 0.0f;
        }
    }
    if (tid < 20) {
        int r = tid / 5, j = tid % 5;
        insm[r][ZS + j] = prev_gen[(b0 + r) * FLATD + j];
    }
    float c1[2] = {0.f, 0.f};  // cell state for rows 2*half, 2*half+1
    float c2[2] = {0.f, 0.f};
    const float fb = fc1_b[u];
    const float4 b1v = ((const float4*)g_b1)[u];
    const float4 b2v = ((const float4*)g_b2)[u];
    // this half's weight bases: [k][u] uint4, local k in [0,128)
    const uint4* w1b = (const uint4*)g_w1 + (size_t)half * 128 * HID + u;
    const uint4* w2b = (const uint4*)g_w2 + (size_t)half * 128 * HID + u;
    const int xoff = half * 64;  // in ulonglong2 units (2 k per element)

    // ring slot pointers (consume: generic; issue: shared-space u32)
    const uint4* consA = ring + 0 * 2048 + tid;
    const uint4* consB = ring + 1 * 2048 + tid;
    const uint4* consC = ring + 2 * 2048 + tid;
    unsigned issA = sm_u32(consA), issB = sm_u32(consB), issC = sm_u32(consC);

    __syncthreads();

    // prologue: prefetch w1 chunks 0,1 into slots A,B
    issue4(issA, w1b + 0 * 4 * HID);
    issue4(issB, w1b + 1 * 4 * HID);

    // pipelined LSTM stage: consume 32 chunks of wc, tail-prefetch wn chunks 0,1
    auto lstm_pipe = [&](const uint4* wc, const uint4* wn, const float2(*Ax)[HID],
                         unsigned long long* acc) {
        const ulonglong2* x0 = (const ulonglong2*)Ax[0] + xoff;
        const ulonglong2* x1 = (const ulonglong2*)Ax[1] + xoff;
        const ulonglong2* x2 = (const ulonglong2*)Ax[2] + xoff;
        const ulonglong2* x3 = (const ulonglong2*)Ax[3] + xoff;
#pragma unroll 1
        for (int c = 0; c < 32; ++c) {
            asm volatile("cp.async.wait_group 1;" ::: "memory");
            uint4 v0 = consA[0];
            uint4 v1 = consA[512];
            uint4 v2 = consA[1024];
            uint4 v3 = consA[1536];
            int j = 2 * c;
            k2_block(v0, v1, x0[j], x1[j], x2[j], x3[j], acc);
            k2_block(v2, v3, x0[j + 1], x1[j + 1], x2[j + 1], x3[j + 1], acc);
            const uint4* src = (c < 30) ? (wc + (c + 2) * 4 * HID)
                                        : (wn + (c - 30) * 4 * HID);
            issue4(issC, src);
            const uint4* tc = consA; consA = consB; consB = consC; consC = tc;
            unsigned ti = issA; issA = issB; issB = issC; issC = ti;
        }
    };

    for (int t = 0; t < SEQL; ++t) {
        // ---- stage 1: stage z rows into smem ----
        if (tid < 4 * ZS) {
            int r = tid / ZS, k = tid % ZS;
            insm[r][k] = z[(size_t)(b0 + r) * (SEQL * ZS) + (size_t)t * ZS + k];
        }
        __syncthreads();  // B1: insm (z + prev) ready

        // ---- stage 2: fc1 + relu -> A1.x  (half0: rows 0,1; half1: rows 2,3) ----
        {
            int r0 = half * 2, r1 = r0 + 1;
            float a0 = fb, a1 = fb;
#pragma unroll 5
            for (int k = 0; k < IN1; k++) {
                float w = g_fc1t[k * HID + u];
                a0 += w * insm[r0][k];
                a1 += w * insm[r1][k];
            }
            A1[r0][u].x = fmaxf(a0, 0.0f);
            A1[r1][u].x = fmaxf(a1, 0.0f);
        }
        __syncthreads();  // B2: A1 = (x, h1prev) ready

        // ---- stage 3: LSTM1 (consumes w1 ring, tail-prefetches w2) ----
        {
            unsigned long long acc[16];
#pragma unroll
            for (int j = 0; j < 16; j++) acc[j] = 0ull;
            lstm_pipe(w1b, w2b, A1, acc);
            // write partials for the OTHER half's rows
            int ro = 2 * (1 - half);
#pragma unroll
            for (int g = 0; g < 4; g++) {
                red[(g * 4 + ro) * HID + u] = redu0(acc[g * 4 + ro]);
                red[(g * 4 + ro + 1) * HID + u] = redu0(acc[g * 4 + ro + 1]);
            }
            __syncthreads();  // B3: partials ready; all A1 reads done
            int rs = 2 * half;
#pragma unroll
            for (int rr = 0; rr < 2; rr++) {
                int r = rs + rr;
                float iv = sigm_f(redu0(acc[0 + r]) + red[(0 + r) * HID + u] + b1v.x);
                float fv = sigm_f(redu0(acc[4 + r]) + red[(4 + r) * HID + u] + b1v.y);
                float gv = tanh_f(redu0(acc[8 + r]) + red[(8 + r) * HID + u] + b1v.z);
                float ov = sigm_f(redu0(acc[12 + r]) + red[(12 + r) * HID + u] + b1v.w);
                float cn = fv * c1[rr] + iv * gv;
                c1[rr] = cn;
                float hv = ov * tanh_f(cn);
                A1[r][u].y = hv;  // h1 for step t+1
                A2[r][u].x = hv;  // h1 input to LSTM2 now
            }
        }
        __syncthreads();  // B4: A2 = (h1, h2prev) ready

        // ---- stage 4: LSTM2 (consumes w2 ring, tail-prefetches next-step w1) ----
        {
            unsigned long long acc[16];
#pragma unroll
            for (int j = 0; j < 16; j++) acc[j] = 0ull;
            lstm_pipe(w2b, w1b, A2, acc);
            int ro = 2 * (1 - half);
#pragma unroll
            for (int g = 0; g < 4; g++) {
                red[(g * 4 + ro) * HID + u] = redu0(acc[g * 4 + ro]);
                red[(g * 4 + ro + 1) * HID + u] = redu0(acc[g * 4 + ro + 1]);
            }
            __syncthreads();  // B5
            int rs = 2 * half;
#pragma unroll
            for (int rr = 0; rr < 2; rr++) {
                int r = rs + rr;
                float iv = sigm_f(redu0(acc[0 + r]) + red[(0 + r) * HID + u] + b2v.x);
                float fv = sigm_f(redu0(acc[4 + r]) + red[(4 + r) * HID + u] + b2v.y);
                float gv = tanh_f(redu0(acc[8 + r]) + red[(8 + r) * HID + u] + b2v.z);
                float ov = sigm_f(redu0(acc[12 + r]) + red[(12 + r) * HID + u] + b2v.w);
                float cn = fv * c2[rr] + iv * gv;
                c2[rr] = cn;
                A2[r][u].y = ov * tanh_f(cn);
            }
        }
        __syncthreads();  // B6: h2 ready

        // ---- stage 5: fc2 + tanh -> prev + output (16 warps, 20 tasks) ----
        {
            int wid = tid >> 5, lane = tid & 31;
            for (int p = wid; p < 20; p += 16) {
                int j = p >> 2, r = p & 3;
                float s = 0.0f;
#pragma unroll
                for (int i = 0; i < 8; i++) {
                    int uu = lane + 32 * i;
                    s += fc2_w[j * HID + uu] * A2[r][uu].y;
                }
#pragma unroll
                for (int o = 16; o; o >>= 1) s += __shfl_down_sync(0xffffffffu, s, o);
                if (lane == 0) {
                    float v = tanh_f(s + fc2_b[j]);
                    insm[r][ZS + j] = v;
                    out[(size_t)(b0 + r) * (SEQL * FLATD) + (size_t)t * FLATD + j] = v;
                }
            }
        }
        // no barrier: stage1(t+1)/stage5 write disjoint insm cells; B1 orders both.
    }
    asm volatile("cp.async.wait_group 0;" ::: "memory");  // drain tail prefetch
}

// ---------------- launch ------------------------------------------------------
extern "C" void kernel_launch(void* const* d_in, const int* in_sizes, int n_in,
                              void* d_out, int out_size) {
    (void)in_sizes; (void)n_in; (void)out_size;
    const float* z        = (const float*)d_in[0];
    const float* prev_gen = (const float*)d_in[1];
    const float* fc1_w    = (const float*)d_in[2];
    const float* fc1_b    = (const float*)d_in[3];
    const float* w_ih1    = (const float*)d_in[4];
    const float* w_hh1    = (const float*)d_in[5];
    const float* b_ih1    = (const float*)d_in[6];
    const float* b_hh1    = (const float*)d_in[7];
    const float* w_ih2    = (const float*)d_in[8];
    const float* w_hh2    = (const float*)d_in[9];
    const float* b_ih2    = (const float*)d_in[10];
    const float* b_hh2    = (const float*)d_in[11];
    const float* fc2_w    = (const float*)d_in[12];
    const float* fc2_b    = (const float*)d_in[13];
    float* out = (float*)d_out;

    const int total = 2 * HID * HID * 4 + 2 * HID * 4 + IN1 * HID;
    repack_kernel<<<(total + 255) / 256, 256>>>(w_ih1, w_hh1, w_ih2, w_hh2,
                                                b_ih1, b_hh1, b_ih2, b_hh2, fc1_w);

    cudaFuncSetAttribute(gen_kernel, cudaFuncAttributeMaxDynamicSharedMemorySize,
                         SMEM_TOTAL);
    gen_kernel<<<BATCH / 4, TPB, SMEM_TOTAL>>>(z, prev_gen, fc1_b, fc2_w, fc2_b, out);
}

// round 12
// speedup vs baseline: 1.1231x; 1.0396x over previous
#include <cuda_runtime.h>
#include <cuda_bf16.h>

#define SEQL 601
#define BATCH 512
#define ZS 100
#define FLATD 5
#define HID 256
#define IN1 105  // ZS + FLATD
#define TPB 512

// ---------------- scratch (__device__ globals; no allocation) ----------------
// LSTM weights repacked to bf16: [k][u][gate], each uint = (bf16 w_ih | bf16 w_hh << 16)
__device__ unsigned g_w1[HID * HID * 4];
__device__ unsigned g_w2[HID * HID * 4];
__device__ float g_b1[HID * 4];      // [u][gate] = b_ih + b_hh  (fp32)
__device__ float g_b2[HID * 4];
__device__ float g_fc1t[IN1 * HID];  // [k][n]  (transposed fc1_w, fp32)

// ---------------- weight repack kernel (cheap, runs every launch) ------------
__global__ void repack_kernel(const float* __restrict__ w_ih1,
                              const float* __restrict__ w_hh1,
                              const float* __restrict__ w_ih2,
                              const float* __restrict__ w_hh2,
                              const float* __restrict__ b_ih1,
                              const float* __restrict__ b_hh1,
                              const float* __restrict__ b_ih2,
                              const float* __restrict__ b_hh2,
                              const float* __restrict__ fc1_w) {
    int idx = blockIdx.x * blockDim.x + threadIdx.x;
    const int NP = HID * HID * 4;  // 262144 pairs per LSTM
    if (idx < 2 * NP) {
        int m = idx / NP;
        int e = idx % NP;
        int g = e & 3;
        int u = (e >> 2) & (HID - 1);
        int k = e >> 10;
        const float* wih = m ? w_ih2 : w_ih1;
        const float* whh = m ? w_hh2 : w_hh1;
        unsigned a = (unsigned)__bfloat16_as_ushort(__float2bfloat16(wih[(g * HID + u) * HID + k]));
        unsigned b = (unsigned)__bfloat16_as_ushort(__float2bfloat16(whh[(g * HID + u) * HID + k]));
        unsigned* dst = m ? g_w2 : g_w1;
        dst[e] = a | (b << 16);
    } else {
        int e = idx - 2 * NP;
        if (e < 2 * HID * 4) {
            int which = e / (HID * 4);
            int r = e % (HID * 4);
            int g = r & 3, u = r >> 2;
            if (which == 0)
                g_b1[r] = b_ih1[g * HID + u] + b_hh1[g * HID + u];
            else
                g_b2[r] = b_ih2[g * HID + u] + b_hh2[g * HID + u];
        } else {
            e -= 2 * HID * 4;
            if (e < IN1 * HID) {
                int n = e % HID, k = e / HID;
                g_fc1t[k * HID + n] = fc1_w[n * IN1 + k];
            }
        }
    }
}

// ---------------- activations -------------------------------------------------
__device__ __forceinline__ float sigm_f(float x) {
    return __fdividef(1.0f, 1.0f + __expf(-x));
}
__device__ __forceinline__ float tanh_f(float x) {
    float e = __expf(-2.0f * x);
    return __fdividef(2.0f, 1.0f + e) - 1.0f;
}

// ---------------- f32x2 helpers -----------------------------------------------
__device__ __forceinline__ unsigned long long cvtw(unsigned c) {
    unsigned lo = c << 16;
    unsigned hi = c & 0xffff0000u;
    unsigned long long p;
    asm("mov.b64 %0, {%1, %2};" : "=l"(p) : "r"(lo), "r"(hi));
    return p;
}
__device__ __forceinline__ void fma2(unsigned long long& acc, unsigned long long w,
                                     unsigned long long xh) {
    asm("fma.rn.f32x2 %0, %1, %2, %3;" : "=l"(acc) : "l"(w), "l"(xh), "l"(acc));
}
__device__ __forceinline__ float redu0(unsigned long long a) {
    unsigned lo, hi;
    asm("mov.b64 {%0, %1}, %2;" : "=r"(lo), "=r"(hi) : "l"(a));
    return __uint_as_float(lo) + __uint_as_float(hi);
}

// ---------------- prefetch helpers ---------------------------------------------
__device__ __forceinline__ void pf_l1(const void* p) {
    asm volatile("prefetch.global.L1 [%0];" :: "l"(p));
}
// Warm this thread's first 4 k2 (8 k-rows, 16B each) of a weight matrix half.
__device__ __forceinline__ void warm8(const uint4* w, int u) {
    const char* p = (const char*)(w + u);
#pragma unroll
    for (int i = 0; i < 8; i++) pf_l1(p + i * 4096);
}

// ---------------- LSTM accumulate over 64 k2-iters (half of K) ----------------
// w  : weight base already offset to this half's first k  ([k][u] uint4)
// x0..x3 : per-row activation pair pointers, offset to this half's first k2
// acc[g*4+r]
__device__ __forceinline__ void lstm_accum(const uint4* __restrict__ w,
                                           const ulonglong2* __restrict__ x0,
                                           const ulonglong2* __restrict__ x1,
                                           const ulonglong2* __restrict__ x2,
                                           const ulonglong2* __restrict__ x3,
                                           int u, unsigned long long* acc) {
    const char* wp = (const char*)(w + u);
#pragma unroll 4
    for (int k2 = 0; k2 < 64; k2++) {
        uint4 wA = *(const uint4*)(wp);
        uint4 wB = *(const uint4*)(wp + 4096);
        // software prefetch 2 k2 (4 k-rows) ahead; immediate offsets, no regs.
        pf_l1(wp + 16384);
        pf_l1(wp + 20480);
        ulonglong2 xv0 = x0[k2];
        ulonglong2 xv1 = x1[k2];
        ulonglong2 xv2 = x2[k2];
        ulonglong2 xv3 = x3[k2];
        unsigned long long wi = cvtw(wA.x);
        unsigned long long wf = cvtw(wA.y);
        unsigned long long wg = cvtw(wA.z);
        unsigned long long wo = cvtw(wA.w);
        fma2(acc[0], wi, xv0.x); fma2(acc[4], wf, xv0.x); fma2(acc[8],  wg, xv0.x); fma2(acc[12], wo, xv0.x);
        fma2(acc[1], wi, xv1.x); fma2(acc[5], wf, xv1.x); fma2(acc[9],  wg, xv1.x); fma2(acc[13], wo, xv1.x);
        fma2(acc[2], wi, xv2.x); fma2(acc[6], wf, xv2.x); fma2(acc[10], wg, xv2.x); fma2(acc[14], wo, xv2.x);
        fma2(acc[3], wi, xv3.x); fma2(acc[7], wf, xv3.x); fma2(acc[11], wg, xv3.x); fma2(acc[15], wo, xv3.x);
        wi = cvtw(wB.x);
        wf = cvtw(wB.y);
        wg = cvtw(wB.z);
        wo = cvtw(wB.w);
        fma2(acc[0], wi, xv0.y); fma2(acc[4], wf, xv0.y); fma2(acc[8],  wg, xv0.y); fma2(acc[12], wo, xv0.y);
        fma2(acc[1], wi, xv1.y); fma2(acc[5], wf, xv1.y); fma2(acc[9],  wg, xv1.y); fma2(acc[13], wo, xv1.y);
        fma2(acc[2], wi, xv2.y); fma2(acc[6], wf, xv2.y); fma2(acc[10], wg, xv2.y); fma2(acc[14], wo, xv2.y);
        fma2(acc[3], wi, xv3.y); fma2(acc[7], wf, xv3.y); fma2(acc[11], wg, xv3.y); fma2(acc[15], wo, xv3.y);
        wp += 8192;
    }
}

// ---------------- main persistent kernel: CTA owns 4 batch rows ---------------
// 512 threads: thread = (u, half). half0: k in [0,128); half1: k in [128,256).
__global__ void __launch_bounds__(TPB, 1) gen_kernel(
    const float* __restrict__ z,         // [B][S][ZS]
    const float* __restrict__ prev_gen,  // [B][FLATD]
    const float* __restrict__ fc1_b,     // [HID]
    const float* __restrict__ fc2_w,     // [FLATD][HID]
    const float* __restrict__ fc2_b,     // [FLATD]
    float* __restrict__ out)             // [B][S][FLATD]
{
    __shared__ __align__(16) float insm[4][112];   // [row][k<105]; [100..104] = prev
    __shared__ __align__(16) float2 A1[4][HID];    // (x_t, h1_{t-1})
    __shared__ __align__(16) float2 A2[4][HID];    // (h1_t, h2_{t-1})
    __shared__ __align__(16) float red[16][HID];   // other-half partial sums [g*4+r][u]

    const int tid = threadIdx.x;
    const int u = tid & (HID - 1);
    const int half = tid >> 8;
    const int b0 = blockIdx.x * 4;

    if (!half) {
#pragma unroll
        for (int r = 0; r < 4; r++) {
            A1[r][u].y = 0.0f;
            A2[r][u].y = 0.0f;
        }
    }
    if (tid < 20) {
        int r = tid / 5, j = tid % 5;
        insm[r][ZS + j] = prev_gen[(b0 + r) * FLATD + j];
    }
    float c1[2] = {0.f, 0.f};  // cell state for rows 2*half, 2*half+1
    float c2[2] = {0.f, 0.f};
    const float fb = fc1_b[u];
    const float4 b1v = ((const float4*)g_b1)[u];
    const float4 b2v = ((const float4*)g_b2)[u];
    // this half's weight/activation base offsets
    const uint4* w1h = (const uint4*)g_w1 + (size_t)half * 128 * HID;
    const uint4* w2h = (const uint4*)g_w2 + (size_t)half * 128 * HID;
    const int xoff = half * 64;  // in ulonglong2 units (2 k per element)

    warm8(w1h, u);  // cover the very first LSTM1 loop entry
    __syncthreads();

    for (int t = 0; t < SEQL; ++t) {
        // ---- stage 1: stage z rows into smem ----
        {
            int e = tid;
            if (e < 4 * ZS) {
                int r = e / ZS, k = e % ZS;
                insm[r][k] = z[(size_t)(b0 + r) * (SEQL * ZS) + (size_t)t * ZS + k];
            }
        }
        __syncthreads();  // B1: insm (z + prev) ready

        // ---- stage 2: fc1 + relu -> A1.x  (half0: rows 0,1; half1: rows 2,3) ----
        {
            int r0 = half * 2, r1 = r0 + 1;
            float a0 = fb, a1 = fb;
#pragma unroll 5
            for (int k = 0; k < IN1; k++) {
                float w = g_fc1t[k * HID + u];
                a0 += w * insm[r0][k];
                a1 += w * insm[r1][k];
            }
            A1[r0][u].x = fmaxf(a0, 0.0f);
            A1[r1][u].x = fmaxf(a1, 0.0f);
        }
        __syncthreads();  // B2: A1 = (x, h1prev) ready

        // ---- stage 3: LSTM1 ----
        {
            unsigned long long acc[16];
#pragma unroll
            for (int j = 0; j < 16; j++) acc[j] = 0ull;
            lstm_accum(w1h, (const ulonglong2*)A1[0] + xoff, (const ulonglong2*)A1[1] + xoff,
                       (const ulonglong2*)A1[2] + xoff, (const ulonglong2*)A1[3] + xoff, u, acc);
            warm8(w2h, u);  // LSTM2 head covered during merge+activations
            // write partials for the OTHER half's rows
            int ro = 2 * (1 - half);
#pragma unroll
            for (int g = 0; g < 4; g++) {
                red[g * 4 + ro][u] = redu0(acc[g * 4 + ro]);
                red[g * 4 + ro + 1][u] = redu0(acc[g * 4 + ro + 1]);
            }
            __syncthreads();  // B3: partials ready; all A1 reads done
            int rs = 2 * half;
#pragma unroll
            for (int rr = 0; rr < 2; rr++) {
                int r = rs + rr;
                float iv = sigm_f(redu0(acc[0 + r]) + red[0 + r][u] + b1v.x);
                float fv = sigm_f(redu0(acc[4 + r]) + red[4 + r][u] + b1v.y);
                float gv = tanh_f(redu0(acc[8 + r]) + red[8 + r][u] + b1v.z);
                float ov = sigm_f(redu0(acc[12 + r]) + red[12 + r][u] + b1v.w);
                float cn = fv * c1[rr] + iv * gv;
                c1[rr] = cn;
                float hv = ov * tanh_f(cn);
                A1[r][u].y = hv;  // h1 for step t+1
                A2[r][u].x = hv;  // h1 input to LSTM2 now
            }
        }
        __syncthreads();  // B4: A2 = (h1, h2prev) ready

        // ---- stage 4: LSTM2 ----
        {
            unsigned long long acc[16];
#pragma unroll
            for (int j = 0; j < 16; j++) acc[j] = 0ull;
            lstm_accum(w2h, (const ulonglong2*)A2[0] + xoff, (const ulonglong2*)A2[1] + xoff,
                       (const ulonglong2*)A2[2] + xoff, (const ulonglong2*)A2[3] + xoff, u, acc);
            warm8(w1h, u);  // next step's LSTM1 head covered by merge+fc2+z phases
            int ro = 2 * (1 - half);
#pragma unroll
            for (int g = 0; g < 4; g++) {
                red[g * 4 + ro][u] = redu0(acc[g * 4 + ro]);
                red[g * 4 + ro + 1][u] = redu0(acc[g * 4 + ro + 1]);
            }
            __syncthreads();  // B5
            int rs = 2 * half;
#pragma unroll
            for (int rr = 0; rr < 2; rr++) {
                int r = rs + rr;
                float iv = sigm_f(redu0(acc[0 + r]) + red[0 + r][u] + b2v.x);
                float fv = sigm_f(redu0(acc[4 + r]) + red[4 + r][u] + b2v.y);
                float gv = tanh_f(redu0(acc[8 + r]) + red[8 + r][u] + b2v.z);
                float ov = sigm_f(redu0(acc[12 + r]) + red[12 + r][u] + b2v.w);
                float cn = fv * c2[rr] + iv * gv;
                c2[rr] = cn;
                A2[r][u].y = ov * tanh_f(cn);
            }
        }
        __syncthreads();  // B6: h2 ready

        // ---- stage 5: fc2 + tanh -> prev + output (16 warps, 20 tasks) ----
        {
            int wid = tid >> 5, lane = tid & 31;
            for (int p = wid; p < 20; p += 16) {
                int j = p >> 2, r = p & 3;
                float s = 0.0f;
#pragma unroll
                for (int i = 0; i < 8; i++) {
                    int uu = lane + 32 * i;
                    s += fc2_w[j * HID + uu] * A2[r][uu].y;
                }
#pragma unroll
                for (int o = 16; o; o >>= 1) s += __shfl_down_sync(0xffffffffu, s, o);
                if (lane == 0) {
                    float v = tanh_f(s + fc2_b[j]);
                    insm[r][ZS + j] = v;
                    out[(size_t)(b0 + r) * (SEQL * FLATD) + (size_t)t * FLATD + j] = v;
                }
            }
        }
        // prefetch next step's z slice (no barrier needed; pure hint)
        if (tid < 4 * ZS && t + 1 < SEQL) {
            int r = tid / ZS, k = tid % ZS;
            pf_l1(&z[(size_t)(b0 + r) * (SEQL * ZS) + (size_t)(t + 1) * ZS + k]);
        }
        // no barrier: stage1(t+1)/stage5 write disjoint insm cells; B1 orders both.
    }
}

// ---------------- launch ------------------------------------------------------
extern "C" void kernel_launch(void* const* d_in, const int* in_sizes, int n_in,
                              void* d_out, int out_size) {
    (void)in_sizes; (void)n_in; (void)out_size;
    const float* z        = (const float*)d_in[0];
    const float* prev_gen = (const float*)d_in[1];
    const float* fc1_w    = (const float*)d_in[2];
    const float* fc1_b    = (const float*)d_in[3];
    const float* w_ih1    = (const float*)d_in[4];
    const float* w_hh1    = (const float*)d_in[5];
    const float* b_ih1    = (const float*)d_in[6];
    const float* b_hh1    = (const float*)d_in[7];
    const float* w_ih2    = (const float*)d_in[8];
    const float* w_hh2    = (const float*)d_in[9];
    const float* b_ih2    = (const float*)d_in[10];
    const float* b_hh2    = (const float*)d_in[11];
    const float* fc2_w    = (const float*)d_in[12];
    const float* fc2_b    = (const float*)d_in[13];
    float* out = (float*)d_out;

    const int total = 2 * HID * HID * 4 + 2 * HID * 4 + IN1 * HID;
    repack_kernel<<<(total + 255) / 256, 256>>>(w_ih1, w_hh1, w_ih2, w_hh2,
                                                b_ih1, b_hh1, b_ih2, b_hh2, fc1_w);

    gen_kernel<<<BATCH / 4, TPB>>>(z, prev_gen, fc1_b, fc2_w, fc2_b, out);
}

// round 13
// speedup vs baseline: 1.1237x; 1.0005x over previous
#include <cuda_runtime.h>
#include <cuda_bf16.h>

#define SEQL 601
#define BATCH 512
#define ZS 100
#define FLATD 5
#define HID 256
#define IN1 105  // ZS + FLATD
#define TPB 512

// ---------------- scratch (__device__ globals; no allocation) ----------------
// LSTM weights repacked to bf16: [k][u][gate], each uint = (bf16 w_ih | bf16 w_hh << 16)
__device__ unsigned g_w1[HID * HID * 4];
__device__ unsigned g_w2[HID * HID * 4];
__device__ float g_b1[HID * 4];      // [u][gate] = b_ih + b_hh  (fp32)
__device__ float g_b2[HID * 4];
__device__ float g_fc1t[IN1 * HID];  // [k][n]  (transposed fc1_w, fp32)

// ---------------- weight repack kernel (cheap, runs every launch) ------------
__global__ void repack_kernel(const float* __restrict__ w_ih1,
                              const float* __restrict__ w_hh1,
                              const float* __restrict__ w_ih2,
                              const float* __restrict__ w_hh2,
                              const float* __restrict__ b_ih1,
                              const float* __restrict__ b_hh1,
                              const float* __restrict__ b_ih2,
                              const float* __restrict__ b_hh2,
                              const float* __restrict__ fc1_w) {
    int idx = blockIdx.x * blockDim.x + threadIdx.x;
    const int NP = HID * HID * 4;  // 262144 pairs per LSTM
    if (idx < 2 * NP) {
        int m = idx / NP;
        int e = idx % NP;
        int g = e & 3;
        int u = (e >> 2) & (HID - 1);
        int k = e >> 10;
        const float* wih = m ? w_ih2 : w_ih1;
        const float* whh = m ? w_hh2 : w_hh1;
        unsigned a = (unsigned)__bfloat16_as_ushort(__float2bfloat16(wih[(g * HID + u) * HID + k]));
        unsigned b = (unsigned)__bfloat16_as_ushort(__float2bfloat16(whh[(g * HID + u) * HID + k]));
        unsigned* dst = m ? g_w2 : g_w1;
        dst[e] = a | (b << 16);
    } else {
        int e = idx - 2 * NP;
        if (e < 2 * HID * 4) {
            int which = e / (HID * 4);
            int r = e % (HID * 4);
            int g = r & 3, u = r >> 2;
            if (which == 0)
                g_b1[r] = b_ih1[g * HID + u] + b_hh1[g * HID + u];
            else
                g_b2[r] = b_ih2[g * HID + u] + b_hh2[g * HID + u];
        } else {
            e -= 2 * HID * 4;
            if (e < IN1 * HID) {
                int n = e % HID, k = e / HID;
                g_fc1t[k * HID + n] = fc1_w[n * IN1 + k];
            }
        }
    }
}

// ---------------- activations -------------------------------------------------
__device__ __forceinline__ float sigm_f(float x) {
    return __fdividef(1.0f, 1.0f + __expf(-x));
}
__device__ __forceinline__ float tanh_f(float x) {
    float e = __expf(-2.0f * x);
    return __fdividef(2.0f, 1.0f + e) - 1.0f;
}

// ---------------- f32x2 helpers -----------------------------------------------
__device__ __forceinline__ unsigned long long cvtw(unsigned c) {
    unsigned lo = c << 16;
    unsigned hi = c & 0xffff0000u;
    unsigned long long p;
    asm("mov.b64 %0, {%1, %2};" : "=l"(p) : "r"(lo), "r"(hi));
    return p;
}
__device__ __forceinline__ void fma2(unsigned long long& acc, unsigned long long w,
                                     unsigned long long xh) {
    asm("fma.rn.f32x2 %0, %1, %2, %3;" : "=l"(acc) : "l"(w), "l"(xh), "l"(acc));
}
__device__ __forceinline__ float redu0(unsigned long long a) {
    unsigned lo, hi;
    asm("mov.b64 {%0, %1}, %2;" : "=r"(lo), "=r"(hi) : "l"(a));
    return __uint_as_float(lo) + __uint_as_float(hi);
}

// ---------------- prefetch helpers ---------------------------------------------
__device__ __forceinline__ void pf_l1(const void* p) {
    asm volatile("prefetch.global.L1 [%0];" :: "l"(p));
}
// Warm this thread's first 4 k2 (8 k-rows, 16B each) of a weight matrix half.
__device__ __forceinline__ void warm8(const uint4* w, int u) {
    const char* p = (const char*)(w + u);
#pragma unroll
    for (int i = 0; i < 8; i++) pf_l1(p + i * 4096);
}

// ---------------- LSTM accumulate over 64 k2-iters (half of K) ----------------
// w  : weight base already offset to this half's first k  ([k][u] uint4)
// x0..x3 : per-row activation pair pointers, offset to this half's first k2
// acc[g*4+r]
__device__ __forceinline__ void lstm_accum(const uint4* __restrict__ w,
                                           const ulonglong2* __restrict__ x0,
                                           const ulonglong2* __restrict__ x1,
                                           const ulonglong2* __restrict__ x2,
                                           const ulonglong2* __restrict__ x3,
                                           int u, unsigned long long* acc) {
    const char* wp = (const char*)(w + u);
#pragma unroll 4
    for (int k2 = 0; k2 < 64; k2++) {
        uint4 wA = *(const uint4*)(wp);
        uint4 wB = *(const uint4*)(wp + 4096);
        // software prefetch 2 k2 (4 k-rows) ahead; immediate offsets, no regs.
        pf_l1(wp + 16384);
        pf_l1(wp + 20480);
        ulonglong2 xv0 = x0[k2];
        ulonglong2 xv1 = x1[k2];
        ulonglong2 xv2 = x2[k2];
        ulonglong2 xv3 = x3[k2];
        unsigned long long wi = cvtw(wA.x);
        unsigned long long wf = cvtw(wA.y);
        unsigned long long wg = cvtw(wA.z);
        unsigned long long wo = cvtw(wA.w);
        fma2(acc[0], wi, xv0.x); fma2(acc[4], wf, xv0.x); fma2(acc[8],  wg, xv0.x); fma2(acc[12], wo, xv0.x);
        fma2(acc[1], wi, xv1.x); fma2(acc[5], wf, xv1.x); fma2(acc[9],  wg, xv1.x); fma2(acc[13], wo, xv1.x);
        fma2(acc[2], wi, xv2.x); fma2(acc[6], wf, xv2.x); fma2(acc[10], wg, xv2.x); fma2(acc[14], wo, xv2.x);
        fma2(acc[3], wi, xv3.x); fma2(acc[7], wf, xv3.x); fma2(acc[11], wg, xv3.x); fma2(acc[15], wo, xv3.x);
        wi = cvtw(wB.x);
        wf = cvtw(wB.y);
        wg = cvtw(wB.z);
        wo = cvtw(wB.w);
        fma2(acc[0], wi, xv0.y); fma2(acc[4], wf, xv0.y); fma2(acc[8],  wg, xv0.y); fma2(acc[12], wo, xv0.y);
        fma2(acc[1], wi, xv1.y); fma2(acc[5], wf, xv1.y); fma2(acc[9],  wg, xv1.y); fma2(acc[13], wo, xv1.y);
        fma2(acc[2], wi, xv2.y); fma2(acc[6], wf, xv2.y); fma2(acc[10], wg, xv2.y); fma2(acc[14], wo, xv2.y);
        fma2(acc[3], wi, xv3.y); fma2(acc[7], wf, xv3.y); fma2(acc[11], wg, xv3.y); fma2(acc[15], wo, xv3.y);
        wp += 8192;
    }
}

// ---------------- main persistent kernel: CTA owns 4 batch rows ---------------
// 512 threads: thread = (u, half). half0: k in [0,128); half1: k in [128,256).
__global__ void __launch_bounds__(TPB, 1) gen_kernel(
    const float* __restrict__ z,         // [B][S][ZS]
    const float* __restrict__ prev_gen,  // [B][FLATD]
    const float* __restrict__ fc1_b,     // [HID]
    const float* __restrict__ fc2_w,     // [FLATD][HID]
    const float* __restrict__ fc2_b,     // [FLATD]
    float* __restrict__ out)             // [B][S][FLATD]
{
    __shared__ __align__(16) float insm[4][112];   // [row][k<105]; [100..104] = prev
    __shared__ __align__(16) float2 A1[4][HID];    // (x_t, h1_{t-1})
    __shared__ __align__(16) float2 A2[4][HID];    // (h1_t, h2_{t-1})
    __shared__ __align__(16) float red[16][HID];   // other-half partial sums [g*4+r][u]

    const int tid = threadIdx.x;
    const int u = tid & (HID - 1);
    const int half = tid >> 8;
    const int b0 = blockIdx.x * 4;

    if (!half) {
#pragma unroll
        for (int r = 0; r < 4; r++) {
            A1[r][u].y = 0.0f;
            A2[r][u].y = 0.0f;
        }
    }
    if (tid < 20) {
        int r = tid / 5, j = tid % 5;
        insm[r][ZS + j] = prev_gen[(b0 + r) * FLATD + j];
    }
    float c1[2] = {0.f, 0.f};  // cell state for rows 2*half, 2*half+1
    float c2[2] = {0.f, 0.f};
    const float fb = fc1_b[u];
    const float4 b1v = ((const float4*)g_b1)[u];
    const float4 b2v = ((const float4*)g_b2)[u];
    // this half's weight/activation base offsets
    const uint4* w1h = (const uint4*)g_w1 + (size_t)half * 128 * HID;
    const uint4* w2h = (const uint4*)g_w2 + (size_t)half * 128 * HID;
    const int xoff = half * 64;  // in ulonglong2 units (2 k per element)

    warm8(w1h, u);  // cover the very first LSTM1 loop entry
    __syncthreads();

    for (int t = 0; t < SEQL; ++t) {
        // ---- stage 1: stage z rows into smem ----
        {
            int e = tid;
            if (e < 4 * ZS) {
                int r = e / ZS, k = e % ZS;
                insm[r][k] = z[(size_t)(b0 + r) * (SEQL * ZS) + (size_t)t * ZS + k];
            }
        }
        __syncthreads();  // B1: insm (z + prev) ready

        // ---- stage 2: fc1 + relu -> A1.x  (half0: rows 0,1; half1: rows 2,3) ----
        {
            int r0 = half * 2, r1 = r0 + 1;
            float a0 = fb, a1 = fb;
#pragma unroll 5
            for (int k = 0; k < IN1; k++) {
                float w = g_fc1t[k * HID + u];
                a0 += w * insm[r0][k];
                a1 += w * insm[r1][k];
            }
            A1[r0][u].x = fmaxf(a0, 0.0f);
            A1[r1][u].x = fmaxf(a1, 0.0f);
        }
        __syncthreads();  // B2: A1 = (x, h1prev) ready

        // ---- stage 3: LSTM1 ----
        {
            unsigned long long acc[16];
#pragma unroll
            for (int j = 0; j < 16; j++) acc[j] = 0ull;
            lstm_accum(w1h, (const ulonglong2*)A1[0] + xoff, (const ulonglong2*)A1[1] + xoff,
                       (const ulonglong2*)A1[2] + xoff, (const ulonglong2*)A1[3] + xoff, u, acc);
            warm8(w2h, u);  // LSTM2 head covered during merge+activations
            // write partials for the OTHER half's rows
            int ro = 2 * (1 - half);
#pragma unroll
            for (int g = 0; g < 4; g++) {
                red[g * 4 + ro][u] = redu0(acc[g * 4 + ro]);
                red[g * 4 + ro + 1][u] = redu0(acc[g * 4 + ro + 1]);
            }
            __syncthreads();  // B3: partials ready; all A1 reads done
            int rs = 2 * half;
#pragma unroll
            for (int rr = 0; rr < 2; rr++) {
                int r = rs + rr;
                float iv = sigm_f(redu0(acc[0 + r]) + red[0 + r][u] + b1v.x);
                float fv = sigm_f(redu0(acc[4 + r]) + red[4 + r][u] + b1v.y);
                float gv = tanh_f(redu0(acc[8 + r]) + red[8 + r][u] + b1v.z);
                float ov = sigm_f(redu0(acc[12 + r]) + red[12 + r][u] + b1v.w);
                float cn = fv * c1[rr] + iv * gv;
                c1[rr] = cn;
                float hv = ov * tanh_f(cn);
                A1[r][u].y = hv;  // h1 for step t+1
                A2[r][u].x = hv;  // h1 input to LSTM2 now
            }
        }
        __syncthreads();  // B4: A2 = (h1, h2prev) ready

        // ---- stage 4: LSTM2 ----
        {
            unsigned long long acc[16];
#pragma unroll
            for (int j = 0; j < 16; j++) acc[j] = 0ull;
            lstm_accum(w2h, (const ulonglong2*)A2[0] + xoff, (const ulonglong2*)A2[1] + xoff,
                       (const ulonglong2*)A2[2] + xoff, (const ulonglong2*)A2[3] + xoff, u, acc);
            warm8(w1h, u);  // next step's LSTM1 head covered by merge+fc2+z phases
            int ro = 2 * (1 - half);
#pragma unroll
            for (int g = 0; g < 4; g++) {
                red[g * 4 + ro][u] = redu0(acc[g * 4 + ro]);
                red[g * 4 + ro + 1][u] = redu0(acc[g * 4 + ro + 1]);
            }
            __syncthreads();  // B5
            int rs = 2 * half;
#pragma unroll
            for (int rr = 0; rr < 2; rr++) {
                int r = rs + rr;
                float iv = sigm_f(redu0(acc[0 + r]) + red[0 + r][u] + b2v.x);
                float fv = sigm_f(redu0(acc[4 + r]) + red[4 + r][u] + b2v.y);
                float gv = tanh_f(redu0(acc[8 + r]) + red[8 + r][u] + b2v.z);
                float ov = sigm_f(redu0(acc[12 + r]) + red[12 + r][u] + b2v.w);
                float cn = fv * c2[rr] + iv * gv;
                c2[rr] = cn;
                A2[r][u].y = ov * tanh_f(cn);
            }
        }
        __syncthreads();  // B6: h2 ready

        // ---- stage 5: fc2 + tanh -> prev + output (16 warps, 20 tasks) ----
        {
            int wid = tid >> 5, lane = tid & 31;
            for (int p = wid; p < 20; p += 16) {
                int j = p >> 2, r = p & 3;
                float s = 0.0f;
#pragma unroll
                for (int i = 0; i < 8; i++) {
                    int uu = lane + 32 * i;
                    s += fc2_w[j * HID + uu] * A2[r][uu].y;
                }
#pragma unroll
                for (int o = 16; o; o >>= 1) s += __shfl_down_sync(0xffffffffu, s, o);
                if (lane == 0) {
                    float v = tanh_f(s + fc2_b[j]);
                    insm[r][ZS + j] = v;
                    out[(size_t)(b0 + r) * (SEQL * FLATD) + (size_t)t * FLATD + j] = v;
                }
            }
        }
        // prefetch next step's z slice (no barrier needed; pure hint)
        if (tid < 4 * ZS && t + 1 < SEQL) {
            int r = tid / ZS, k = tid % ZS;
            pf_l1(&z[(size_t)(b0 + r) * (SEQL * ZS) + (size_t)(t + 1) * ZS + k]);
        }
        // no barrier: stage1(t+1)/stage5 write disjoint insm cells; B1 orders both.
    }
}

// ---------------- launch ------------------------------------------------------
extern "C" void kernel_launch(void* const* d_in, const int* in_sizes, int n_in,
                              void* d_out, int out_size) {
    (void)in_sizes; (void)n_in; (void)out_size;
    const float* z        = (const float*)d_in[0];
    const float* prev_gen = (const float*)d_in[1];
    const float* fc1_w    = (const float*)d_in[2];
    const float* fc1_b    = (const float*)d_in[3];
    const float* w_ih1    = (const float*)d_in[4];
    const float* w_hh1    = (const float*)d_in[5];
    const float* b_ih1    = (const float*)d_in[6];
    const float* b_hh1    = (const float*)d_in[7];
    const float* w_ih2    = (const float*)d_in[8];
    const float* w_hh2    = (const float*)d_in[9];
    const float* b_ih2    = (const float*)d_in[10];
    const float* b_hh2    = (const float*)d_in[11];
    const float* fc2_w    = (const float*)d_in[12];
    const float* fc2_b    = (const float*)d_in[13];
    float* out = (float*)d_out;

    const int total = 2 * HID * HID * 4 + 2 * HID * 4 + IN1 * HID;
    repack_kernel<<<(total + 255) / 256, 256>>>(w_ih1, w_hh1, w_ih2, w_hh2,
                                                b_ih1, b_hh1, b_ih2, b_hh2, fc1_w);

    gen_kernel<<<BATCH / 4, TPB>>>(z, prev_gen, fc1_b, fc2_w, fc2_b, out);
}